// round 1
// baseline (speedup 1.0000x reference)
#include <cuda_runtime.h>

// Problem constants (fixed by setup_inputs)
#define TT 4
#define BB 16
#define CC 512
#define HWW 1024
#define NELEM (4u*16u*512u*1024u)   // 33,554,432

// Scratch (device globals — no allocation allowed)
__device__ float g_qpre[33554432];
__device__ float g_kpre[33554432];
__device__ float g_y[33554432];
// proj pre-activations reuse g_qpre (q_pre fully consumed by kernel 2)

// ---------------------------------------------------------------------------
// Kernel 1: fused dual GEMM  q_pre = BN(q_w @ x), k_pre = BN(k_w @ x)
// per batch (t*B+b): out[o,hw] = sum_c w[o,c] * x[c,hw]
// ---------------------------------------------------------------------------
constexpr int BM = 64, BN = 64, BK = 16;

__global__ __launch_bounds__(256) void qk_gemm_kernel(
    const float* __restrict__ x,
    const float* __restrict__ qw, const float* __restrict__ kw,
    const float* __restrict__ qg, const float* __restrict__ qb,
    const float* __restrict__ qm, const float* __restrict__ qv,
    const float* __restrict__ kg, const float* __restrict__ kb,
    const float* __restrict__ km, const float* __restrict__ kv)
{
    __shared__ float Aq[BK][BM];
    __shared__ float Ak[BK][BM];
    __shared__ float Bs[BK][BN];

    const int tid   = threadIdx.x;
    const int n0    = blockIdx.x * BN;
    const int m0    = blockIdx.y * BM;
    const int batch = blockIdx.z;

    const float* xb = x       + (size_t)batch * CC * HWW;
    float*       qo = g_qpre  + (size_t)batch * CC * HWW;
    float*       ko = g_kpre  + (size_t)batch * CC * HWW;

    const int a_m = tid >> 2;            // 0..63
    const int a_k = (tid & 3) * 4;       // 0,4,8,12
    const int b_k = tid >> 4;            // 0..15
    const int b_n = (tid & 15) * 4;      // 0..60

    const int tx = tid & 15, ty = tid >> 4;

    float accq[4][4];
    float acck[4][4];
    #pragma unroll
    for (int i = 0; i < 4; i++)
        #pragma unroll
        for (int j = 0; j < 4; j++) { accq[i][j] = 0.f; acck[i][j] = 0.f; }

    for (int k0 = 0; k0 < CC; k0 += BK) {
        float4 laq = *(const float4*)&qw[(size_t)(m0 + a_m) * CC + k0 + a_k];
        float4 lak = *(const float4*)&kw[(size_t)(m0 + a_m) * CC + k0 + a_k];
        float4 lb  = *(const float4*)&xb[(size_t)(k0 + b_k) * HWW + n0 + b_n];
        __syncthreads();
        Aq[a_k + 0][a_m] = laq.x; Aq[a_k + 1][a_m] = laq.y;
        Aq[a_k + 2][a_m] = laq.z; Aq[a_k + 3][a_m] = laq.w;
        Ak[a_k + 0][a_m] = lak.x; Ak[a_k + 1][a_m] = lak.y;
        Ak[a_k + 2][a_m] = lak.z; Ak[a_k + 3][a_m] = lak.w;
        *(float4*)&Bs[b_k][b_n] = lb;
        __syncthreads();

        #pragma unroll
        for (int k = 0; k < BK; k++) {
            float aqv[4], akv[4], bv[4];
            *(float4*)aqv = *(const float4*)&Aq[k][ty * 4];
            *(float4*)akv = *(const float4*)&Ak[k][ty * 4];
            *(float4*)bv  = *(const float4*)&Bs[k][tx * 4];
            #pragma unroll
            for (int i = 0; i < 4; i++)
                #pragma unroll
                for (int j = 0; j < 4; j++) {
                    accq[i][j] += aqv[i] * bv[j];
                    acck[i][j] += akv[i] * bv[j];
                }
        }
    }

    #pragma unroll
    for (int i = 0; i < 4; i++) {
        const int o = m0 + ty * 4 + i;
        const float invq = qg[o] / sqrtf(qv[o] + 1e-5f);
        const float shq  = qb[o] - qm[o] * invq;
        const float invk = kg[o] / sqrtf(kv[o] + 1e-5f);
        const float shk  = kb[o] - km[o] * invk;
        float4 oq, ok;
        oq.x = accq[i][0] * invq + shq; oq.y = accq[i][1] * invq + shq;
        oq.z = accq[i][2] * invq + shq; oq.w = accq[i][3] * invq + shq;
        ok.x = acck[i][0] * invk + shk; ok.y = acck[i][1] * invk + shk;
        ok.z = acck[i][2] * invk + shk; ok.w = acck[i][3] * invk + shk;
        *(float4*)&qo[(size_t)o * HWW + n0 + tx * 4] = oq;
        *(float4*)&ko[(size_t)o * HWW + n0 + tx * 4] = ok;
    }
}

// ---------------------------------------------------------------------------
// Kernel 2: LIF(q_pre), LIF(k_pre), head-sum of q spikes, attn LIF (thr 0.5),
//           y = attn_spike * k_spike
// block: (hw tile of 32) x (batch b); 512 threads = 32 hw-lanes x 16 ch-groups
// each thread owns 32 channels' membrane state across the T loop
// ---------------------------------------------------------------------------
__global__ __launch_bounds__(512) void lif_gate_kernel()
{
    const int tid = threadIdx.x;
    const int hwi = tid & 31;
    const int cg  = tid >> 5;            // 0..15 -> channels [cg*32, cg*32+32)
    const int hw0 = blockIdx.x * 32;
    const int b   = blockIdx.y;

    __shared__ float part[16][32];
    __shared__ float vattn[8][32];
    __shared__ float aspk[8][32];

    if (tid < 256) vattn[tid >> 5][tid & 31] = 0.f;

    float vq[32], vk[32];
    #pragma unroll
    for (int j = 0; j < 32; j++) { vq[j] = 0.f; vk[j] = 0.f; }
    __syncthreads();

    for (int t = 0; t < TT; t++) {
        const size_t base =
            (((size_t)t * BB + b) * CC + (size_t)cg * 32) * HWW + hw0 + hwi;

        // q-branch LIF + partial head sum
        float ssum = 0.f;
        #pragma unroll
        for (int j = 0; j < 32; j++) {
            const float xq = g_qpre[base + (size_t)j * HWW];
            float v = vq[j] + (xq - vq[j]) * 0.5f;
            const float s = (v >= 1.0f) ? 1.f : 0.f;
            vq[j] = v * (1.f - s);
            ssum += s;
        }
        part[cg][hwi] = ssum;
        __syncthreads();

        // attn LIF per (head, hw): head h sums ch-groups 2h, 2h+1
        if (tid < 256) {
            const int h = tid >> 5, w2 = tid & 31;
            const float s = part[2 * h][w2] + part[2 * h + 1][w2];
            float v = vattn[h][w2];
            v = v + (s - v) * 0.5f;
            const float a = (v >= 0.5f) ? 1.f : 0.f;
            vattn[h][w2] = v * (1.f - a);
            aspk[h][w2]  = a;
        }
        __syncthreads();

        // k-branch LIF + gate + write y
        const float a = aspk[cg >> 1][hwi];
        #pragma unroll
        for (int j = 0; j < 32; j++) {
            const float xk = g_kpre[base + (size_t)j * HWW];
            float v = vk[j] + (xk - vk[j]) * 0.5f;
            const float s = (v >= 1.0f) ? 1.f : 0.f;
            vk[j] = v * (1.f - s);
            g_y[base + (size_t)j * HWW] = a * s;
        }
        __syncthreads();
    }
}

// ---------------------------------------------------------------------------
// Kernel 3: proj GEMM  proj_pre = BN(proj_w @ y + proj_b)  -> stored in g_qpre
// ---------------------------------------------------------------------------
__global__ __launch_bounds__(256) void proj_gemm_kernel(
    const float* __restrict__ pw, const float* __restrict__ pbias,
    const float* __restrict__ pg, const float* __restrict__ pbeta,
    const float* __restrict__ pm, const float* __restrict__ pv)
{
    __shared__ float As[BK][BM];
    __shared__ float Bs[BK][BN];

    const int tid   = threadIdx.x;
    const int n0    = blockIdx.x * BN;
    const int m0    = blockIdx.y * BM;
    const int batch = blockIdx.z;

    const float* yb = g_y    + (size_t)batch * CC * HWW;
    float*       po = g_qpre + (size_t)batch * CC * HWW;

    const int a_m = tid >> 2;
    const int a_k = (tid & 3) * 4;
    const int b_k = tid >> 4;
    const int b_n = (tid & 15) * 4;
    const int tx = tid & 15, ty = tid >> 4;

    float acc[4][4];
    #pragma unroll
    for (int i = 0; i < 4; i++)
        #pragma unroll
        for (int j = 0; j < 4; j++) acc[i][j] = 0.f;

    for (int k0 = 0; k0 < CC; k0 += BK) {
        float4 la = *(const float4*)&pw[(size_t)(m0 + a_m) * CC + k0 + a_k];
        float4 lb = *(const float4*)&yb[(size_t)(k0 + b_k) * HWW + n0 + b_n];
        __syncthreads();
        As[a_k + 0][a_m] = la.x; As[a_k + 1][a_m] = la.y;
        As[a_k + 2][a_m] = la.z; As[a_k + 3][a_m] = la.w;
        *(float4*)&Bs[b_k][b_n] = lb;
        __syncthreads();

        #pragma unroll
        for (int k = 0; k < BK; k++) {
            float av[4], bv[4];
            *(float4*)av = *(const float4*)&As[k][ty * 4];
            *(float4*)bv = *(const float4*)&Bs[k][tx * 4];
            #pragma unroll
            for (int i = 0; i < 4; i++)
                #pragma unroll
                for (int j = 0; j < 4; j++)
                    acc[i][j] += av[i] * bv[j];
        }
    }

    #pragma unroll
    for (int i = 0; i < 4; i++) {
        const int o = m0 + ty * 4 + i;
        const float inv = pg[o] / sqrtf(pv[o] + 1e-5f);
        const float sh  = pbeta[o] - pm[o] * inv;
        const float bia = pbias[o];
        float4 ov;
        ov.x = (acc[i][0] + bia) * inv + sh;
        ov.y = (acc[i][1] + bia) * inv + sh;
        ov.z = (acc[i][2] + bia) * inv + sh;
        ov.w = (acc[i][3] + bia) * inv + sh;
        *(float4*)&po[(size_t)o * HWW + n0 + tx * 4] = ov;
    }
}

// ---------------------------------------------------------------------------
// Kernel 4: final LIF over proj_pre (in g_qpre) -> out spikes
// ---------------------------------------------------------------------------
__global__ __launch_bounds__(256) void lif_out_kernel(float* __restrict__ out)
{
    const size_t stride4 = (size_t)BB * CC * HWW / 4;   // 2,097,152 float4 / t
    const size_t i = (size_t)blockIdx.x * blockDim.x + threadIdx.x;
    if (i >= stride4) return;

    const float4* pp = (const float4*)g_qpre;
    float4*       oo = (float4*)out;

    float4 v; v.x = v.y = v.z = v.w = 0.f;
    #pragma unroll
    for (int t = 0; t < TT; t++) {
        const float4 xx = pp[(size_t)t * stride4 + i];
        float4 s;
        v.x = v.x + (xx.x - v.x) * 0.5f; s.x = (v.x >= 1.f) ? 1.f : 0.f; v.x *= (1.f - s.x);
        v.y = v.y + (xx.y - v.y) * 0.5f; s.y = (v.y >= 1.f) ? 1.f : 0.f; v.y *= (1.f - s.y);
        v.z = v.z + (xx.z - v.z) * 0.5f; s.z = (v.z >= 1.f) ? 1.f : 0.f; v.z *= (1.f - s.z);
        v.w = v.w + (xx.w - v.w) * 0.5f; s.w = (v.w >= 1.f) ? 1.f : 0.f; v.w *= (1.f - s.w);
        oo[(size_t)t * stride4 + i] = s;
    }
}

// ---------------------------------------------------------------------------
// Launch
// ---------------------------------------------------------------------------
extern "C" void kernel_launch(void* const* d_in, const int* in_sizes, int n_in,
                              void* d_out, int out_size)
{
    const float* x   = (const float*)d_in[0];
    const float* qw  = (const float*)d_in[1];
    const float* qg  = (const float*)d_in[2];
    const float* qb  = (const float*)d_in[3];
    const float* qm  = (const float*)d_in[4];
    const float* qv  = (const float*)d_in[5];
    const float* kw  = (const float*)d_in[6];
    const float* kg  = (const float*)d_in[7];
    const float* kb  = (const float*)d_in[8];
    const float* km  = (const float*)d_in[9];
    const float* kv  = (const float*)d_in[10];
    const float* pw  = (const float*)d_in[11];
    const float* pbias = (const float*)d_in[12];
    const float* pg  = (const float*)d_in[13];
    const float* pbeta = (const float*)d_in[14];
    const float* pm  = (const float*)d_in[15];
    const float* pv  = (const float*)d_in[16];

    dim3 gemm_grid(HWW / BN, CC / BM, TT * BB);   // (16, 8, 64)

    qk_gemm_kernel<<<gemm_grid, 256>>>(x, qw, kw, qg, qb, qm, qv, kg, kb, km, kv);
    lif_gate_kernel<<<dim3(32, BB), 512>>>();
    proj_gemm_kernel<<<gemm_grid, 256>>>(pw, pbias, pg, pbeta, pm, pv);

    const int n4 = (int)((size_t)BB * CC * HWW / 4);
    lif_out_kernel<<<(n4 + 255) / 256, 256>>>((float*)d_out);
}

// round 3
// speedup vs baseline: 1.4642x; 1.4642x over previous
#include <cuda_runtime.h>

// Problem constants (fixed by setup_inputs)
#define TT 4
#define BB 16
#define CC 512
#define HWW 1024

// Scratch (device globals — no allocation allowed)
__device__ float g_qpre[33554432];
__device__ float g_kpre[33554432];
__device__ float g_y[33554432];

// ---------------------------------------------------------------------------
// packed fp32x2 FMA (Blackwell FFMA2) — bit-exact IEEE fp32 per lane
// ---------------------------------------------------------------------------
__device__ __forceinline__ void fma2(unsigned long long& d,
                                     unsigned long long a,
                                     unsigned long long b) {
    asm("fma.rn.f32x2 %0, %1, %2, %0;" : "+l"(d) : "l"(a), "l"(b));
}

__device__ __forceinline__ float2 ull2f2(unsigned long long v) {
    float2 f;
    asm("mov.b64 {%0, %1}, %2;" : "=f"(f.x), "=f"(f.y) : "l"(v));
    return f;
}

// ---------------------------------------------------------------------------
// GEMM: out[o,hw] = BN( sum_c W[o,c] * In[c,hw] (+ bias[o]) )
// BM=BN=128, BK=16, 256 threads, 8x8 per thread, f32x2 packed accumulators.
// A tile stored PRE-DUPLICATED in shared ((a,a) per element) so the inner
// loop is pure LDS.128 + fma.f32x2.
// SRC_Y: 0 -> read from arg `in` (x); 1 -> read from g_y
// DST:   0 -> write g_qpre; 1 -> write g_kpre
// ---------------------------------------------------------------------------
constexpr int GBM = 128, GBN = 128, GBK = 16;

template <bool HAS_BIAS, int SRC_Y, int DST>
__global__ __launch_bounds__(256, 2) void gemm_bn_kernel(
    const float* __restrict__ in_arg,  // [64, C, HW] batched B operand (x)
    const float* __restrict__ w,       // [C, C] A operand
    const float* __restrict__ bias,    // [C] or nullptr
    const float* __restrict__ gmm,     // gamma
    const float* __restrict__ bet,     // beta
    const float* __restrict__ mea,     // mean
    const float* __restrict__ var)     // var
{
    __shared__ float2 As2[GBK][GBM];   // duplicated A: 16 KB
    __shared__ float  Bs[GBK][GBN];    // 8 KB

    const int tid   = threadIdx.x;
    const int n0    = blockIdx.x * GBN;
    const int m0    = blockIdx.y * GBM;
    const int batch = blockIdx.z;

    const float* in  = SRC_Y ? (const float*)g_y : in_arg;
    float*       out = (DST == 0) ? g_qpre : g_kpre;

    const float* inb  = in  + (size_t)batch * CC * HWW;
    float*       outb = out + (size_t)batch * CC * HWW;

    // A loader: each thread 8 consecutive k's of one row m
    const int a_m = tid >> 1;              // 0..127
    const int a_k = (tid & 1) * 8;         // 0 or 8
    // B loader: each thread 8 consecutive n's of one row k
    const int b_k = tid >> 4;              // 0..15
    const int b_n = (tid & 15) * 8;        // 0..120

    const int tx = tid & 15;               // n-tile: tx*8
    const int ty = tid >> 4;               // m-tile: ty*8

    unsigned long long acc[8][4];
    #pragma unroll
    for (int i = 0; i < 8; i++)
        #pragma unroll
        for (int j = 0; j < 4; j++) acc[i][j] = 0ull;

    // prefetch tile 0
    float4 pa0 = *(const float4*)&w[(size_t)(m0 + a_m) * CC + a_k];
    float4 pa1 = *(const float4*)&w[(size_t)(m0 + a_m) * CC + a_k + 4];
    float4 pb0 = *(const float4*)&inb[(size_t)b_k * HWW + n0 + b_n];
    float4 pb1 = *(const float4*)&inb[(size_t)b_k * HWW + n0 + b_n + 4];

    for (int k0 = 0; k0 < CC; k0 += GBK) {
        __syncthreads();
        As2[a_k + 0][a_m] = make_float2(pa0.x, pa0.x);
        As2[a_k + 1][a_m] = make_float2(pa0.y, pa0.y);
        As2[a_k + 2][a_m] = make_float2(pa0.z, pa0.z);
        As2[a_k + 3][a_m] = make_float2(pa0.w, pa0.w);
        As2[a_k + 4][a_m] = make_float2(pa1.x, pa1.x);
        As2[a_k + 5][a_m] = make_float2(pa1.y, pa1.y);
        As2[a_k + 6][a_m] = make_float2(pa1.z, pa1.z);
        As2[a_k + 7][a_m] = make_float2(pa1.w, pa1.w);
        *(float4*)&Bs[b_k][b_n]     = pb0;
        *(float4*)&Bs[b_k][b_n + 4] = pb1;
        __syncthreads();

        if (k0 + GBK < CC) {
            const int kn = k0 + GBK;
            pa0 = *(const float4*)&w[(size_t)(m0 + a_m) * CC + kn + a_k];
            pa1 = *(const float4*)&w[(size_t)(m0 + a_m) * CC + kn + a_k + 4];
            pb0 = *(const float4*)&inb[(size_t)(kn + b_k) * HWW + n0 + b_n];
            pb1 = *(const float4*)&inb[(size_t)(kn + b_k) * HWW + n0 + b_n + 4];
        }

        #pragma unroll
        for (int k = 0; k < GBK; k++) {
            // 8 duplicated a's = 4 x LDS.128
            ulonglong2 a01 = *(const ulonglong2*)&As2[k][ty * 8 + 0];
            ulonglong2 a23 = *(const ulonglong2*)&As2[k][ty * 8 + 2];
            ulonglong2 a45 = *(const ulonglong2*)&As2[k][ty * 8 + 4];
            ulonglong2 a67 = *(const ulonglong2*)&As2[k][ty * 8 + 6];
            // 8 b's = 2 x LDS.128, natural pairs
            ulonglong2 b03 = *(const ulonglong2*)&Bs[k][tx * 8];
            ulonglong2 b47 = *(const ulonglong2*)&Bs[k][tx * 8 + 4];

            unsigned long long av[8] = {a01.x, a01.y, a23.x, a23.y,
                                        a45.x, a45.y, a67.x, a67.y};
            unsigned long long bv[4] = {b03.x, b03.y, b47.x, b47.y};

            #pragma unroll
            for (int i = 0; i < 8; i++) {
                fma2(acc[i][0], av[i], bv[0]);
                fma2(acc[i][1], av[i], bv[1]);
                fma2(acc[i][2], av[i], bv[2]);
                fma2(acc[i][3], av[i], bv[3]);
            }
        }
    }

    #pragma unroll
    for (int i = 0; i < 8; i++) {
        const int o = m0 + ty * 8 + i;
        const float inv = gmm[o] / sqrtf(var[o] + 1e-5f);
        const float sh  = bet[o] - mea[o] * inv;
        const float bi  = HAS_BIAS ? bias[o] : 0.f;

        float2 p0 = ull2f2(acc[i][0]);
        float2 p1 = ull2f2(acc[i][1]);
        float2 p2 = ull2f2(acc[i][2]);
        float2 p3 = ull2f2(acc[i][3]);
        float4 o0, o1;
        o0.x = (p0.x + bi) * inv + sh; o0.y = (p0.y + bi) * inv + sh;
        o0.z = (p1.x + bi) * inv + sh; o0.w = (p1.y + bi) * inv + sh;
        o1.x = (p2.x + bi) * inv + sh; o1.y = (p2.y + bi) * inv + sh;
        o1.z = (p3.x + bi) * inv + sh; o1.w = (p3.y + bi) * inv + sh;
        *(float4*)&outb[(size_t)o * HWW + n0 + tx * 8]     = o0;
        *(float4*)&outb[(size_t)o * HWW + n0 + tx * 8 + 4] = o1;
    }
}

// ---------------------------------------------------------------------------
// Kernel 2: LIF(q_pre), LIF(k_pre), head-sum of q spikes, attn LIF (thr 0.5),
//           y = attn_spike * k_spike
// ---------------------------------------------------------------------------
__global__ __launch_bounds__(512) void lif_gate_kernel()
{
    const int tid = threadIdx.x;
    const int hwi = tid & 31;
    const int cg  = tid >> 5;            // 0..15 -> channels [cg*32, cg*32+32)
    const int hw0 = blockIdx.x * 32;
    const int b   = blockIdx.y;

    __shared__ float part[16][32];
    __shared__ float vattn[8][32];
    __shared__ float aspk[8][32];

    if (tid < 256) vattn[tid >> 5][tid & 31] = 0.f;

    float vq[32], vk[32];
    #pragma unroll
    for (int j = 0; j < 32; j++) { vq[j] = 0.f; vk[j] = 0.f; }
    __syncthreads();

    for (int t = 0; t < TT; t++) {
        const size_t base =
            (((size_t)t * BB + b) * CC + (size_t)cg * 32) * HWW + hw0 + hwi;

        float ssum = 0.f;
        #pragma unroll
        for (int j = 0; j < 32; j++) {
            const float xq = g_qpre[base + (size_t)j * HWW];
            float v = vq[j] + (xq - vq[j]) * 0.5f;
            const float s = (v >= 1.0f) ? 1.f : 0.f;
            vq[j] = v * (1.f - s);
            ssum += s;
        }
        part[cg][hwi] = ssum;
        __syncthreads();

        if (tid < 256) {
            const int h = tid >> 5, w2 = tid & 31;
            const float s = part[2 * h][w2] + part[2 * h + 1][w2];
            float v = vattn[h][w2];
            v = v + (s - v) * 0.5f;
            const float a = (v >= 0.5f) ? 1.f : 0.f;
            vattn[h][w2] = v * (1.f - a);
            aspk[h][w2]  = a;
        }
        __syncthreads();

        const float a = aspk[cg >> 1][hwi];
        #pragma unroll
        for (int j = 0; j < 32; j++) {
            const float xk = g_kpre[base + (size_t)j * HWW];
            float v = vk[j] + (xk - vk[j]) * 0.5f;
            const float s = (v >= 1.0f) ? 1.f : 0.f;
            vk[j] = v * (1.f - s);
            g_y[base + (size_t)j * HWW] = a * s;
        }
        __syncthreads();
    }
}

// ---------------------------------------------------------------------------
// Kernel 4: final LIF over proj_pre (in g_kpre) -> out spikes
// ---------------------------------------------------------------------------
__global__ __launch_bounds__(256) void lif_out_kernel(float* __restrict__ out)
{
    const size_t stride4 = (size_t)BB * CC * HWW / 4;
    const size_t i = (size_t)blockIdx.x * blockDim.x + threadIdx.x;
    if (i >= stride4) return;

    const float4* pp = (const float4*)g_kpre;
    float4*       oo = (float4*)out;

    float4 v; v.x = v.y = v.z = v.w = 0.f;
    #pragma unroll
    for (int t = 0; t < TT; t++) {
        const float4 xx = pp[(size_t)t * stride4 + i];
        float4 s;
        v.x = v.x + (xx.x - v.x) * 0.5f; s.x = (v.x >= 1.f) ? 1.f : 0.f; v.x *= (1.f - s.x);
        v.y = v.y + (xx.y - v.y) * 0.5f; s.y = (v.y >= 1.f) ? 1.f : 0.f; v.y *= (1.f - s.y);
        v.z = v.z + (xx.z - v.z) * 0.5f; s.z = (v.z >= 1.f) ? 1.f : 0.f; v.z *= (1.f - s.z);
        v.w = v.w + (xx.w - v.w) * 0.5f; s.w = (v.w >= 1.f) ? 1.f : 0.f; v.w *= (1.f - s.w);
        oo[(size_t)t * stride4 + i] = s;
    }
}

// ---------------------------------------------------------------------------
// Launch
// ---------------------------------------------------------------------------
extern "C" void kernel_launch(void* const* d_in, const int* in_sizes, int n_in,
                              void* d_out, int out_size)
{
    const float* x     = (const float*)d_in[0];
    const float* qw    = (const float*)d_in[1];
    const float* qg    = (const float*)d_in[2];
    const float* qb    = (const float*)d_in[3];
    const float* qm    = (const float*)d_in[4];
    const float* qv    = (const float*)d_in[5];
    const float* kw    = (const float*)d_in[6];
    const float* kg    = (const float*)d_in[7];
    const float* kb    = (const float*)d_in[8];
    const float* km    = (const float*)d_in[9];
    const float* kv    = (const float*)d_in[10];
    const float* pw    = (const float*)d_in[11];
    const float* pbias = (const float*)d_in[12];
    const float* pg    = (const float*)d_in[13];
    const float* pbeta = (const float*)d_in[14];
    const float* pm    = (const float*)d_in[15];
    const float* pv    = (const float*)d_in[16];

    dim3 grid(HWW / GBN, CC / GBM, TT * BB);   // (8, 4, 64)

    // q: x -> g_qpre,  k: x -> g_kpre
    gemm_bn_kernel<false, 0, 0><<<grid, 256>>>(x, qw, nullptr, qg, qb, qm, qv);
    gemm_bn_kernel<false, 0, 1><<<grid, 256>>>(x, kw, nullptr, kg, kb, km, kv);
    lif_gate_kernel<<<dim3(32, BB), 512>>>();
    // proj: g_y -> g_kpre
    gemm_bn_kernel<true, 1, 1><<<grid, 256>>>(nullptr, pw, pbias, pg, pbeta, pm, pv);

    const int n4 = (int)((size_t)BB * CC * HWW / 4);
    lif_out_kernel<<<(n4 + 255) / 256, 256>>>((float*)d_out);
}

// round 11
// speedup vs baseline: 1.7099x; 1.1679x over previous
#include <cuda_runtime.h>

// Problem constants (fixed by setup_inputs)
#define TT 4
#define BB 16
#define CC 512
#define HWW 1024

// Scratch (device globals — no allocation allowed)
__device__ float g_qpre[33554432];
__device__ float g_kpre[33554432];
__device__ float g_y[33554432];

// ---------------------------------------------------------------------------
// packed fp32x2 FMA (Blackwell FFMA2) — bit-exact IEEE fp32 per lane
// ---------------------------------------------------------------------------
__device__ __forceinline__ void fma2(unsigned long long& d,
                                     unsigned long long a,
                                     unsigned long long b) {
    asm("fma.rn.f32x2 %0, %1, %2, %0;" : "+l"(d) : "l"(a), "l"(b));
}

__device__ __forceinline__ float2 ull2f2(unsigned long long v) {
    float2 f;
    asm("mov.b64 {%0, %1}, %2;" : "=f"(f.x), "=f"(f.y) : "l"(v));
    return f;
}

__device__ __forceinline__ unsigned long long dup2(float a) {
    unsigned long long r;
    asm("mov.b64 %0, {%1, %1};" : "=l"(r) : "f"(a));
    return r;
}

// ---------------------------------------------------------------------------
// GEMM: out[o,hw] = BN( sum_c W[o,c] * In[c,hw] (+ bias[o]) )
// BM=BN=128, BK=16, 256 threads, 8x8 per thread, f32x2 packed accumulators.
// A stored plain in smem; (a,a) packs built via mov.b64 (ALU pipe).
// Double-buffered smem tiles: one __syncthreads per k-tile.
// SRC_Y: 0 -> read from arg `in` (x); 1 -> read from g_y
// DST:   0 -> write g_qpre; 1 -> write g_kpre
// ---------------------------------------------------------------------------
constexpr int GBM = 128, GBN = 128, GBK = 16;
constexpr int NT  = CC / GBK;   // 32 k-tiles

template <bool HAS_BIAS, int SRC_Y, int DST>
__global__ __launch_bounds__(256, 2) void gemm_bn_kernel(
    const float* __restrict__ in_arg,  // [64, C, HW] batched B operand (x)
    const float* __restrict__ w,       // [C, C] A operand
    const float* __restrict__ bias,    // [C] or nullptr
    const float* __restrict__ gmm,     // gamma
    const float* __restrict__ bet,     // beta
    const float* __restrict__ mea,     // mean
    const float* __restrict__ var)     // var
{
    __shared__ float As[2][GBK][GBM];  // 8 KB per buffer
    __shared__ float Bs[2][GBK][GBN];  // 8 KB per buffer

    const int tid   = threadIdx.x;
    const int n0    = blockIdx.x * GBN;
    const int m0    = blockIdx.y * GBM;
    const int batch = blockIdx.z;

    const float* in  = SRC_Y ? (const float*)g_y : in_arg;
    float*       out = (DST == 0) ? g_qpre : g_kpre;

    const float* inb  = in  + (size_t)batch * CC * HWW;
    float*       outb = out + (size_t)batch * CC * HWW;

    // A loader: thread loads 8 consecutive k's of one row m
    const int a_m = tid >> 1;              // 0..127
    const int a_k = (tid & 1) * 8;         // 0 or 8
    // B loader: thread loads 8 consecutive n's of one row k
    const int b_k = tid >> 4;              // 0..15
    const int b_n = (tid & 15) * 8;        // 0..120

    const int tx = tid & 15;               // n-tile: tx*8
    const int ty = tid >> 4;               // m-tile: ty*8

    unsigned long long acc[8][4];
    #pragma unroll
    for (int i = 0; i < 8; i++)
        #pragma unroll
        for (int j = 0; j < 4; j++) acc[i][j] = 0ull;

    const float* wrow = &w[(size_t)(m0 + a_m) * CC + a_k];
    const float* brow = &inb[(size_t)b_k * HWW + n0 + b_n];

    // load + store tile 0
    {
        float4 pa0 = *(const float4*)(wrow);
        float4 pa1 = *(const float4*)(wrow + 4);
        float4 pb0 = *(const float4*)(brow);
        float4 pb1 = *(const float4*)(brow + 4);
        As[0][a_k + 0][a_m] = pa0.x; As[0][a_k + 1][a_m] = pa0.y;
        As[0][a_k + 2][a_m] = pa0.z; As[0][a_k + 3][a_m] = pa0.w;
        As[0][a_k + 4][a_m] = pa1.x; As[0][a_k + 5][a_m] = pa1.y;
        As[0][a_k + 6][a_m] = pa1.z; As[0][a_k + 7][a_m] = pa1.w;
        *(float4*)&Bs[0][b_k][b_n]     = pb0;
        *(float4*)&Bs[0][b_k][b_n + 4] = pb1;
    }
    __syncthreads();

    for (int t = 0; t < NT; t++) {
        const int p = t & 1;

        // prefetch tile t+1 into registers (overlaps with compute below)
        float4 pa0, pa1, pb0, pb1;
        if (t + 1 < NT) {
            const int kn = (t + 1) * GBK;
            pa0 = *(const float4*)(wrow + kn);
            pa1 = *(const float4*)(wrow + kn + 4);
            pb0 = *(const float4*)(brow + (size_t)kn * HWW);
            pb1 = *(const float4*)(brow + (size_t)kn * HWW + 4);
        }

        #pragma unroll
        for (int k = 0; k < GBK; k++) {
            // A: 8 plain floats (2 x LDS.128, broadcast-friendly)
            float4 af0 = *(const float4*)&As[p][k][ty * 8];
            float4 af1 = *(const float4*)&As[p][k][ty * 8 + 4];
            // B: 8 floats = 4 natural f32x2 pairs (2 x LDS.128)
            ulonglong2 b03 = *(const ulonglong2*)&Bs[p][k][tx * 8];
            ulonglong2 b47 = *(const ulonglong2*)&Bs[p][k][tx * 8 + 4];

            unsigned long long av[8];
            av[0] = dup2(af0.x); av[1] = dup2(af0.y);
            av[2] = dup2(af0.z); av[3] = dup2(af0.w);
            av[4] = dup2(af1.x); av[5] = dup2(af1.y);
            av[6] = dup2(af1.z); av[7] = dup2(af1.w);
            unsigned long long bv[4] = {b03.x, b03.y, b47.x, b47.y};

            #pragma unroll
            for (int i = 0; i < 8; i++) {
                fma2(acc[i][0], av[i], bv[0]);
                fma2(acc[i][1], av[i], bv[1]);
                fma2(acc[i][2], av[i], bv[2]);
                fma2(acc[i][3], av[i], bv[3]);
            }
        }

        if (t + 1 < NT) {
            const int q = p ^ 1;
            As[q][a_k + 0][a_m] = pa0.x; As[q][a_k + 1][a_m] = pa0.y;
            As[q][a_k + 2][a_m] = pa0.z; As[q][a_k + 3][a_m] = pa0.w;
            As[q][a_k + 4][a_m] = pa1.x; As[q][a_k + 5][a_m] = pa1.y;
            As[q][a_k + 6][a_m] = pa1.z; As[q][a_k + 7][a_m] = pa1.w;
            *(float4*)&Bs[q][b_k][b_n]     = pb0;
            *(float4*)&Bs[q][b_k][b_n + 4] = pb1;
            __syncthreads();
        }
    }

    #pragma unroll
    for (int i = 0; i < 8; i++) {
        const int o = m0 + ty * 8 + i;
        const float inv = gmm[o] / sqrtf(var[o] + 1e-5f);
        const float sh  = bet[o] - mea[o] * inv;
        const float bi  = HAS_BIAS ? bias[o] : 0.f;

        float2 p0 = ull2f2(acc[i][0]);
        float2 p1 = ull2f2(acc[i][1]);
        float2 p2 = ull2f2(acc[i][2]);
        float2 p3 = ull2f2(acc[i][3]);
        float4 o0, o1;
        o0.x = (p0.x + bi) * inv + sh; o0.y = (p0.y + bi) * inv + sh;
        o0.z = (p1.x + bi) * inv + sh; o0.w = (p1.y + bi) * inv + sh;
        o1.x = (p2.x + bi) * inv + sh; o1.y = (p2.y + bi) * inv + sh;
        o1.z = (p3.x + bi) * inv + sh; o1.w = (p3.y + bi) * inv + sh;
        *(float4*)&outb[(size_t)o * HWW + n0 + tx * 8]     = o0;
        *(float4*)&outb[(size_t)o * HWW + n0 + tx * 8 + 4] = o1;
    }
}

// ---------------------------------------------------------------------------
// Kernel 2: LIF(q_pre), LIF(k_pre), head-sum of q spikes, attn LIF (thr 0.5),
//           y = attn_spike * k_spike
// ---------------------------------------------------------------------------
__global__ __launch_bounds__(512) void lif_gate_kernel()
{
    const int tid = threadIdx.x;
    const int hwi = tid & 31;
    const int cg  = tid >> 5;            // 0..15 -> channels [cg*32, cg*32+32)
    const int hw0 = blockIdx.x * 32;
    const int b   = blockIdx.y;

    __shared__ float part[16][32];
    __shared__ float vattn[8][32];
    __shared__ float aspk[8][32];

    if (tid < 256) vattn[tid >> 5][tid & 31] = 0.f;

    float vq[32], vk[32];
    #pragma unroll
    for (int j = 0; j < 32; j++) { vq[j] = 0.f; vk[j] = 0.f; }
    __syncthreads();

    for (int t = 0; t < TT; t++) {
        const size_t base =
            (((size_t)t * BB + b) * CC + (size_t)cg * 32) * HWW + hw0 + hwi;

        float ssum = 0.f;
        #pragma unroll
        for (int j = 0; j < 32; j++) {
            const float xq = g_qpre[base + (size_t)j * HWW];
            float v = vq[j] + (xq - vq[j]) * 0.5f;
            const float s = (v >= 1.0f) ? 1.f : 0.f;
            vq[j] = v * (1.f - s);
            ssum += s;
        }
        part[cg][hwi] = ssum;
        __syncthreads();

        if (tid < 256) {
            const int h = tid >> 5, w2 = tid & 31;
            const float s = part[2 * h][w2] + part[2 * h + 1][w2];
            float v = vattn[h][w2];
            v = v + (s - v) * 0.5f;
            const float a = (v >= 0.5f) ? 1.f : 0.f;
            vattn[h][w2] = v * (1.f - a);
            aspk[h][w2]  = a;
        }
        __syncthreads();

        const float a = aspk[cg >> 1][hwi];
        #pragma unroll
        for (int j = 0; j < 32; j++) {
            const float xk = g_kpre[base + (size_t)j * HWW];
            float v = vk[j] + (xk - vk[j]) * 0.5f;
            const float s = (v >= 1.0f) ? 1.f : 0.f;
            vk[j] = v * (1.f - s);
            g_y[base + (size_t)j * HWW] = a * s;
        }
        __syncthreads();
    }
}

// ---------------------------------------------------------------------------
// Kernel 4: final LIF over proj_pre (in g_kpre) -> out spikes
// ---------------------------------------------------------------------------
__global__ __launch_bounds__(256) void lif_out_kernel(float* __restrict__ out)
{
    const size_t stride4 = (size_t)BB * CC * HWW / 4;
    const size_t i = (size_t)blockIdx.x * blockDim.x + threadIdx.x;
    if (i >= stride4) return;

    const float4* pp = (const float4*)g_kpre;
    float4*       oo = (float4*)out;

    float4 v; v.x = v.y = v.z = v.w = 0.f;
    #pragma unroll
    for (int t = 0; t < TT; t++) {
        const float4 xx = pp[(size_t)t * stride4 + i];
        float4 s;
        v.x = v.x + (xx.x - v.x) * 0.5f; s.x = (v.x >= 1.f) ? 1.f : 0.f; v.x *= (1.f - s.x);
        v.y = v.y + (xx.y - v.y) * 0.5f; s.y = (v.y >= 1.f) ? 1.f : 0.f; v.y *= (1.f - s.y);
        v.z = v.z + (xx.z - v.z) * 0.5f; s.z = (v.z >= 1.f) ? 1.f : 0.f; v.z *= (1.f - s.z);
        v.w = v.w + (xx.w - v.w) * 0.5f; s.w = (v.w >= 1.f) ? 1.f : 0.f; v.w *= (1.f - s.w);
        oo[(size_t)t * stride4 + i] = s;
    }
}

// ---------------------------------------------------------------------------
// Launch
// ---------------------------------------------------------------------------
extern "C" void kernel_launch(void* const* d_in, const int* in_sizes, int n_in,
                              void* d_out, int out_size)
{
    const float* x     = (const float*)d_in[0];
    const float* qw    = (const float*)d_in[1];
    const float* qg    = (const float*)d_in[2];
    const float* qb    = (const float*)d_in[3];
    const float* qm    = (const float*)d_in[4];
    const float* qv    = (const float*)d_in[5];
    const float* kw    = (const float*)d_in[6];
    const float* kg    = (const float*)d_in[7];
    const float* kb    = (const float*)d_in[8];
    const float* km    = (const float*)d_in[9];
    const float* kv    = (const float*)d_in[10];
    const float* pw    = (const float*)d_in[11];
    const float* pbias = (const float*)d_in[12];
    const float* pg    = (const float*)d_in[13];
    const float* pbeta = (const float*)d_in[14];
    const float* pm    = (const float*)d_in[15];
    const float* pv    = (const float*)d_in[16];

    dim3 grid(HWW / GBN, CC / GBM, TT * BB);   // (8, 4, 64)

    // q: x -> g_qpre,  k: x -> g_kpre
    gemm_bn_kernel<false, 0, 0><<<grid, 256>>>(x, qw, nullptr, qg, qb, qm, qv);
    gemm_bn_kernel<false, 0, 1><<<grid, 256>>>(x, kw, nullptr, kg, kb, km, kv);
    lif_gate_kernel<<<dim3(32, BB), 512>>>();
    // proj: g_y -> g_kpre
    gemm_bn_kernel<true, 1, 1><<<grid, 256>>>(nullptr, pw, pbias, pg, pbeta, pm, pv);

    const int n4 = (int)((size_t)BB * CC * HWW / 4);
    lif_out_kernel<<<(n4 + 255) / 256, 256>>>((float*)d_out);
}